// round 14
// baseline (speedup 1.0000x reference)
#include <cuda_runtime.h>
#include <cuda_fp16.h>
#include <cstdint>

// Problem constants
#define BATCH 4
#define HH 1080
#define WW 1920
#define NLUT 33
#define HW (HH * WW)                 // 2,073,600
#define PAIRS_PER (NLUT * NLUT * 32) // 34,848 half2 entries per (b,c)
#define NQUADS (PAIRS_PER / 4)       // 8,712 16-byte quads
#define NCOMBO 12                    // 4 batches * 3 channels
#define SUBS 12                      // CTAs per combo
#define TPB 1024

// LUT staging: chunk the 33*33=1089 rows (33 floats each) of one (b,c) slice.
// A build quad reads 5 consecutive floats WITHIN one row, so row-granular
// chunks have no cross-chunk reads.
#define ROWS_TOTAL (NLUT * NLUT)     // 1089
#define RPC 273                      // rows per chunk
#define NCH 4                        // 273*4 = 1092 >= 1089
#define CHUNK_F (RPC * NLUT)         // 9009 floats = 36,036 B
#define TABLE_BYTES (PAIRS_PER * 4)  // 139,392
#define SMEM_TOTAL (TABLE_BYTES + 2 * CHUNK_F * 4) // 211,464 B

__device__ __forceinline__ void cp_async4(unsigned int smem_addr, const void* gptr) {
    asm volatile("cp.async.ca.shared.global [%0], [%1], 4;\n"
                 :: "r"(smem_addr), "l"(gptr) : "memory");
}

__device__ __forceinline__ float tap(const __half2* __restrict__ sp,
                                     float x, float y, float z) {
    // __saturatef clamps to [0,1]; scale by 31.999998 (vs exact 32) so
    // i0 <= 31 always, keeping the +32 / +1056 / +1088 offsets in-bounds.
    // Trilinear interp is continuous across cell boundaries, so the 6e-8
    // relative coordinate perturbation is ~1e-6 in the output — far below
    // the table's fp16 quantization (~1e-4).
    float fx = __saturatef(x) * 31.999998f;
    float fy = __saturatef(y) * 31.999998f;
    float fz = __saturatef(z) * 31.999998f;
    int ix = (int)fx;
    int iy = (int)fy;
    int iz = (int)fz;
    float wx = fx - (float)ix;
    float wy = fy - (float)iy;
    float wz = fz - (float)iz;

    int base = (iz * NLUT + iy) * 32 + ix;
    __half2 q00 = sp[base];                  // (z0,y0): x0,x1 packed
    __half2 q01 = sp[base + 32];             // (z0,y1)
    __half2 q10 = sp[base + NLUT * 32];      // (z1,y0)
    __half2 q11 = sp[base + NLUT * 32 + 32]; // (z1,y1)

    float2 a00 = __half22float2(q00);
    float2 a01 = __half22float2(q01);
    float2 a10 = __half22float2(q10);
    float2 a11 = __half22float2(q11);

    float c00 = fmaf(wx, a00.y - a00.x, a00.x);
    float c01 = fmaf(wx, a01.y - a01.x, a01.x);
    float c10 = fmaf(wx, a10.y - a10.x, a10.x);
    float c11 = fmaf(wx, a11.y - a11.x, a11.x);
    float c0 = fmaf(wy, c01 - c00, c00);
    float c1 = fmaf(wy, c11 - c10, c10);
    return fmaf(wz, c1 - c0, c0);
}

__global__ void __launch_bounds__(TPB, 1)
lut_apply_kernel(const float* __restrict__ img,
                 const float* __restrict__ lut,
                 float* __restrict__ out) {
    extern __shared__ char smem[];
    __half2* s_pairs = reinterpret_cast<__half2*>(smem);
    float* sbuf[2] = { reinterpret_cast<float*>(smem + TABLE_BYTES),
                       reinterpret_cast<float*>(smem + TABLE_BYTES) + CHUNK_F };

    const int combo = blockIdx.x % NCOMBO; // interleave: same-batch CTAs co-run (L2 reuse)
    const int sub = blockIdx.x / NCOMBO;   // 0..SUBS-1
    const int b = combo / 3;
    const int c = combo % 3;

    const float4* cx = reinterpret_cast<const float4*>(img + (size_t)b * 3 * HW);
    const float4* cy = cx + HW / 4;
    const float4* cz = cy + HW / 4;
    float4* o4 = reinterpret_cast<float4*>(out + (size_t)(b * 3 + c) * HW);

    const int npix4 = HW / 4;     // 518,400
    const int stride = SUBS * TPB;

    // Iteration 0's image loads first — their DRAM latency overlaps the
    // table build below.
    int p = sub * TPB + threadIdx.x;   // always < npix4
    float4 X = cx[p];
    float4 Y = cy[p];
    float4 Z = cz[p];

    // ---- Double-buffered async build of the x-pair fp16 table ----
    // cp.async stages lut rows into smem scratch (4B granularity: combo
    // slices are only 4B-aligned) while the previous chunk converts from
    // smem scratch into the table (5 LDS.32 -> 1 STS.128 per quad).
    // Register footprint during build ~20 live — the main loop's 51 stays
    // the high-water mark (R10/R12 pressure calibration).
    {
        const float* lslice = lut + (size_t)combo * (NLUT * NLUT * NLUT);
        unsigned int sbuf_addr[2];
        asm("{ .reg .u64 t; cvta.to.shared.u64 t, %1; cvt.u32.u64 %0, t; }"
            : "=r"(sbuf_addr[0]) : "l"(sbuf[0]));
        asm("{ .reg .u64 t; cvta.to.shared.u64 t, %1; cvt.u32.u64 %0, t; }"
            : "=r"(sbuf_addr[1]) : "l"(sbuf[1]));
        uint4* dst = reinterpret_cast<uint4*>(s_pairs);

        // stage chunk 0
        {
            const float* src = lslice;
#pragma unroll
            for (int k = 0; k < 9; k++) {
                int i = threadIdx.x + k * TPB;
                if (i < CHUNK_F) cp_async4(sbuf_addr[0] + i * 4, src + i);
            }
            asm volatile("cp.async.commit_group;\n" ::: "memory");
        }

#pragma unroll
        for (int ch = 0; ch < NCH; ch++) {
            // stage chunk ch+1 into the other buffer
            if (ch < NCH - 1) {
                const float* src = lslice + (ch + 1) * CHUNK_F;
                int nf = (ch + 1 == NCH - 1)
                           ? (ROWS_TOTAL - (NCH - 1) * RPC) * NLUT  // 8910
                           : CHUNK_F;
#pragma unroll
                for (int k = 0; k < 9; k++) {
                    int i = threadIdx.x + k * TPB;
                    if (i < nf) cp_async4(sbuf_addr[(ch + 1) & 1] + i * 4, src + i);
                }
                asm volatile("cp.async.commit_group;\n" ::: "memory");
                asm volatile("cp.async.wait_group 1;\n" ::: "memory"); // chunk ch done
            } else {
                asm volatile("cp.async.wait_group 0;\n" ::: "memory");
            }
            __syncthreads();  // chunk ch visible to all threads

            // convert chunk ch: smem scratch -> fp16 pair table
            const float* buf = sbuf[ch & 1];
            int nrows = (ch == NCH - 1) ? (ROWS_TOTAL - (NCH - 1) * RPC) : RPC;
            int nq = nrows * 8;            // quads in this chunk (8/row)
            int qbase = ch * RPC * 8;
#pragma unroll
            for (int j = 0; j < 3; j++) {
                int lq = threadIdx.x + j * TPB;
                if (lq < nq) {
                    int lt = lq >> 3;          // local row
                    int xq = (lq & 7) << 2;    // x0 = 0,4,...,28
                    const float* row = buf + lt * NLUT + xq;
                    float v0 = row[0];
                    float v1 = row[1];
                    float v2 = row[2];
                    float v3 = row[3];
                    float v4 = row[4];
                    union { __half2 h[4]; uint4 u; } pk;
                    pk.h[0] = __floats2half2_rn(v0, v1);
                    pk.h[1] = __floats2half2_rn(v1, v2);
                    pk.h[2] = __floats2half2_rn(v2, v3);
                    pk.h[3] = __floats2half2_rn(v3, v4);
                    dst[qbase + lq] = pk.u;
                }
            }
            __syncthreads();  // all reads of buf[ch&1] done before restaging it
        }
    }

    // Software-pipelined main loop (unchanged — at its measured floor):
    // next iteration's global loads issue before this iteration's LDS-heavy
    // tap work consumes the current data. Taps stay in function form —
    // wider live ranges spill or thrash the 64-reg cap (R6/R8/R10).
#pragma unroll 1
    for (; p < npix4; p += stride) {
        int pn = min(p + stride, npix4 - 1);  // branchless prefetch guard
        float4 Xn = cx[pn];
        float4 Yn = cy[pn];
        float4 Zn = cz[pn];

        float4 R;
        R.x = tap(s_pairs, X.x, Y.x, Z.x);
        R.y = tap(s_pairs, X.y, Y.y, Z.y);
        R.z = tap(s_pairs, X.z, Y.z, Z.z);
        R.w = tap(s_pairs, X.w, Y.w, Z.w);
        o4[p] = R;

        X = Xn; Y = Yn; Z = Zn;
    }
}

extern "C" void kernel_launch(void* const* d_in, const int* in_sizes, int n_in,
                              void* d_out, int out_size) {
    const float* img = (const float*)d_in[0]; // (4,3,1080,1920) f32
    const float* lut = (const float*)d_in[1]; // (4,3,33,33,33) f32
    float* out = (float*)d_out;

    cudaFuncSetAttribute(lut_apply_kernel,
                         cudaFuncAttributeMaxDynamicSharedMemorySize, SMEM_TOTAL);

    lut_apply_kernel<<<NCOMBO * SUBS, TPB, SMEM_TOTAL>>>(img, lut, out);
}

// round 15
// speedup vs baseline: 1.0917x; 1.0917x over previous
#include <cuda_runtime.h>
#include <cuda_fp16.h>
#include <cstdint>

// Problem constants
#define BATCH 4
#define HH 1080
#define WW 1920
#define NLUT 33
#define HW (HH * WW)                 // 2,073,600
#define PAIRS_PER (NLUT * NLUT * 32) // 34,848 half2 entries per (b,c)
#define NQUADS (PAIRS_PER / 4)       // 8,712 16-byte quads
#define NCOMBO 12                    // 4 batches * 3 channels
#define SMEM_BYTES (PAIRS_PER * 4)   // 139,392 B
#define SUBS 12                      // CTAs per combo
#define TPB 1024

__device__ __forceinline__ float tap(const __half2* __restrict__ sp,
                                     float x, float y, float z) {
    // __saturatef clamps to [0,1]; scale by 31.999998 (vs exact 32) so
    // i0 <= 31 always, keeping the +32 / +1056 / +1088 offsets in-bounds.
    // Trilinear interp is continuous across cell boundaries, so the 6e-8
    // relative coordinate perturbation is ~1e-6 in the output — far below
    // the table's fp16 quantization (~1e-4).
    float fx = __saturatef(x) * 31.999998f;
    float fy = __saturatef(y) * 31.999998f;
    float fz = __saturatef(z) * 31.999998f;
    int ix = (int)fx;
    int iy = (int)fy;
    int iz = (int)fz;
    float wx = fx - (float)ix;
    float wy = fy - (float)iy;
    float wz = fz - (float)iz;

    int base = (iz * NLUT + iy) * 32 + ix;
    __half2 q00 = sp[base];                  // (z0,y0): x0,x1 packed
    __half2 q01 = sp[base + 32];             // (z0,y1)
    __half2 q10 = sp[base + NLUT * 32];      // (z1,y0)
    __half2 q11 = sp[base + NLUT * 32 + 32]; // (z1,y1)

    float2 a00 = __half22float2(q00);
    float2 a01 = __half22float2(q01);
    float2 a10 = __half22float2(q10);
    float2 a11 = __half22float2(q11);

    float c00 = fmaf(wx, a00.y - a00.x, a00.x);
    float c01 = fmaf(wx, a01.y - a01.x, a01.x);
    float c10 = fmaf(wx, a10.y - a10.x, a10.x);
    float c11 = fmaf(wx, a11.y - a11.x, a11.x);
    float c0 = fmaf(wy, c01 - c00, c00);
    float c1 = fmaf(wy, c11 - c10, c10);
    return fmaf(wz, c1 - c0, c0);
}

__global__ void __launch_bounds__(TPB, 1)
lut_apply_kernel(const float* __restrict__ img,
                 const float* __restrict__ lut,
                 float* __restrict__ out) {
    extern __shared__ __half2 s_pairs[];
    const int combo = blockIdx.x % NCOMBO; // interleave: same-batch CTAs co-run (L2 reuse)
    const int sub = blockIdx.x / NCOMBO;   // 0..SUBS-1
    const int b = combo / 3;
    const int c = combo % 3;

    const float4* cx = reinterpret_cast<const float4*>(img + (size_t)b * 3 * HW);
    const float4* cy = cx + HW / 4;
    const float4* cz = cy + HW / 4;
    float4* o4 = reinterpret_cast<float4*>(out + (size_t)(b * 3 + c) * HW);

    const int npix4 = HW / 4;     // 518,400
    const int stride = SUBS * TPB;

    // Iteration 0's image loads first — their DRAM latency overlaps the
    // table build below.
    int p = sub * TPB + threadIdx.x;   // always < npix4
    float4 X = cx[p];
    float4 Y = cy[p];
    float4 Z = cz[p];

    // Build this combo's x-pair fp16 table directly from the fp32 lut
    // (fused; no separate build kernel, no global scratch, no smem
    // round-trip — R14's cp.async double-buffer was strictly worse).
    // QUAD-vectorized: 4 consecutive pairs from 5 scalar loads row[0..4]
    // (lut rows are 33 floats — float4-unaligned, but the 5 independent
    // LDG.32 hit 1-2 L1 lines), committed with ONE STS.128.
    // Pressure recipe (R10/R11/R12 calibration): inner 5 unrolled
    // (25 loads in flight, ~30 live regs < main loop's 51 high-water),
    // outer 2 rolled.
    {
        const float* lslice = lut + (size_t)combo * (NLUT * NLUT * NLUT);
        uint4* dst = reinterpret_cast<uint4*>(s_pairs);
#pragma unroll 1
        for (int ko = 0; ko < 2; ko++) {
#pragma unroll
            for (int kj = 0; kj < 5; kj++) {
                int qi = threadIdx.x + (ko * 5 + kj) * TPB;
                if (qi < NQUADS) {
                    int t = qi >> 3;           // row = z*33 + y (8 quads/row)
                    int xq = (qi & 7) << 2;    // x0 = 0,4,...,28
                    const float* row = lslice + t * NLUT + xq;
                    float v0 = row[0];
                    float v1 = row[1];
                    float v2 = row[2];
                    float v3 = row[3];
                    float v4 = row[4];
                    union { __half2 h[4]; uint4 u; } pk;
                    pk.h[0] = __floats2half2_rn(v0, v1);
                    pk.h[1] = __floats2half2_rn(v1, v2);
                    pk.h[2] = __floats2half2_rn(v2, v3);
                    pk.h[3] = __floats2half2_rn(v3, v4);
                    dst[qi] = pk.u;
                }
            }
        }
    }
    __syncthreads();

    // Software-pipelined main loop (FROZEN — measured floor 57.7us across
    // R6/R8/R9/R13): next iteration's global loads issue before this
    // iteration's LDS-heavy tap work consumes the current data. Taps stay
    // in function form — wider live ranges spill or thrash the 64-reg cap
    // (R6/R8/R10).
#pragma unroll 1
    for (; p < npix4; p += stride) {
        int pn = min(p + stride, npix4 - 1);  // branchless prefetch guard
        float4 Xn = cx[pn];
        float4 Yn = cy[pn];
        float4 Zn = cz[pn];

        float4 R;
        R.x = tap(s_pairs, X.x, Y.x, Z.x);
        R.y = tap(s_pairs, X.y, Y.y, Z.y);
        R.z = tap(s_pairs, X.z, Y.z, Z.z);
        R.w = tap(s_pairs, X.w, Y.w, Z.w);
        o4[p] = R;

        X = Xn; Y = Yn; Z = Zn;
    }
}

extern "C" void kernel_launch(void* const* d_in, const int* in_sizes, int n_in,
                              void* d_out, int out_size) {
    const float* img = (const float*)d_in[0]; // (4,3,1080,1920) f32
    const float* lut = (const float*)d_in[1]; // (4,3,33,33,33) f32
    float* out = (float*)d_out;

    cudaFuncSetAttribute(lut_apply_kernel,
                         cudaFuncAttributeMaxDynamicSharedMemorySize, SMEM_BYTES);

    lut_apply_kernel<<<NCOMBO * SUBS, TPB, SMEM_BYTES>>>(img, lut, out);
}